// round 14
// baseline (speedup 1.0000x reference)
#include <cuda_runtime.h>
#include <cuda_fp16.h>
#include <stdint.h>

#define D      1024
#define NROWS  65536
#define DD     (D * D)

// GEMM tile: 128x128, BK=64, 3-stage cp.async, ldmatrix + XOR swizzle
#define TBK     64
#define KT      (D / TBK)        // 16
#define STAGEB  32768            // (128 rows A + 128 rows B) * 64 halves * 2B
#define SMEMSZ  (3 * STAGEB + 1024)

// ---------------- scratch (static device globals; ALL 256B-aligned) ------------
__device__ __align__(256) __half g_xh[(size_t)NROWS * D];
__device__ __align__(256) __half g_Ah  [2 * DD];   // a = 10A
__device__ __align__(256) __half g_Bneg[2 * DD];   // -a
__device__ __align__(256) __half g_P2[2 * DD];     // a^2
__device__ __align__(256) __half g_ET[2 * DD];     // E^T = 0.1 a^2 - a
__device__ __align__(256) __half g_M [2 * DD];     // M1 | M2  (U = I + M)
__device__ __align__(256) __half g_Wa [DD];        // Rot (I + M1)
__device__ __align__(256) __half g_WaT[DD];        // Wa^T
__device__ __align__(256) __half g_W  [DD];        // U2 Rot U1
__device__ __align__(256) float  g_part[2 * D];
__device__ __align__(256) float  g_pass[1];

__device__ __forceinline__ uint32_t smem_u32(const void* p) {
    return (uint32_t)__cvta_generic_to_shared(p);
}
#define LDSM_X4(r0, r1, r2, r3, addr) \
    asm volatile("ldmatrix.sync.aligned.m8n8.x4.shared.b16 {%0,%1,%2,%3}, [%4];" \
                 : "=r"(r0), "=r"(r1), "=r"(r2), "=r"(r3) : "r"(addr))
#define MMA16816(c0,c1,c2,c3,a0,a1,a2,a3,b0,b1) \
    asm volatile("mma.sync.aligned.m16n8k16.row.col.f32.f16.f16.f32 " \
        "{%0,%1,%2,%3}, {%4,%5,%6,%7}, {%8,%9}, {%0,%1,%2,%3};\n" \
        : "+f"(c0), "+f"(c1), "+f"(c2), "+f"(c3) \
        : "r"(a0), "r"(a1), "r"(a2), "r"(a3), "r"(b0), "r"(b1))

// ================= GEMM mainloop (64x32 warp tile, 256 threads) ==================
struct GemmCtx {
    uint32_t sbase;
    int tid, wr, wc, grp, q, lrow, lk;
};

__device__ __forceinline__ GemmCtx make_ctx(uint32_t sbase) {
    GemmCtx cx;
    cx.sbase = sbase;
    cx.tid = threadIdx.x;
    int w = cx.tid >> 5, lane = cx.tid & 31;
    cx.wr = w >> 2; cx.wc = w & 3;
    cx.grp = lane >> 2; cx.q = lane & 3;
    cx.lrow = lane & 15; cx.lk = lane >> 4;
    return cx;
}

__device__ __forceinline__ void gemm_main(const GemmCtx& cx,
                                          const __half* __restrict__ A,
                                          const __half* __restrict__ B,
                                          size_t rowBase, int colBase,
                                          float acc[4][4][4])
{
    #pragma unroll
    for (int a = 0; a < 4; a++)
        #pragma unroll
        for (int b = 0; b < 4; b++)
            #pragma unroll
            for (int c = 0; c < 4; c++) acc[a][b][c] = 0.f;

    auto load_tile = [&](int kt) {
        const int stage = kt % 3;
        const int k0 = kt * TBK;
        #pragma unroll
        for (int i = 0; i < 8; i++) {
            int id  = cx.tid + (i << 8);
            int isB = id >> 10;
            int rc  = id & 1023;
            int row = rc >> 3, c = rc & 7;
            uint32_t sw = ((uint32_t)row << 7) | (((uint32_t)(c ^ (row & 7))) << 4);
            const __half* g = (isB ? (B + (size_t)(colBase + row) * D)
                                   : (A + (rowBase + row) * (size_t)D)) + k0 + (c << 3);
            uint32_t s = cx.sbase + stage * STAGEB + (isB << 14) + sw;
            asm volatile("cp.async.cg.shared.global [%0], [%1], 16;\n" :: "r"(s), "l"(g));
        }
        asm volatile("cp.async.commit_group;\n");
    };

    load_tile(0);
    load_tile(1);

    for (int kt = 0; kt < KT; kt++) {
        if (kt == KT - 1) asm volatile("cp.async.wait_group 0;\n");
        else              asm volatile("cp.async.wait_group 1;\n");
        __syncthreads();
        if (kt + 2 < KT) load_tile(kt + 2);

        const uint32_t aS = cx.sbase + (kt % 3) * STAGEB;
        const uint32_t bS = aS + 16384;

        #pragma unroll
        for (int kp = 0; kp < 4; kp++) {
            const uint32_t ch = (uint32_t)(kp * 2 + cx.lk);
            uint32_t a[4][4];
            #pragma unroll
            for (int mi = 0; mi < 4; mi++) {
                int row = cx.wr * 64 + mi * 16 + cx.lrow;
                uint32_t ad = aS + ((uint32_t)row << 7) + ((ch ^ (uint32_t)(row & 7)) << 4);
                LDSM_X4(a[mi][0], a[mi][1], a[mi][2], a[mi][3], ad);
            }
            uint32_t b[4][2];
            #pragma unroll
            for (int np = 0; np < 2; np++) {
                int row = cx.wc * 32 + np * 16 + cx.lrow;
                uint32_t bd = bS + ((uint32_t)row << 7) + ((ch ^ (uint32_t)(row & 7)) << 4);
                uint32_t r0, r1, r2, r3;
                LDSM_X4(r0, r1, r2, r3, bd);
                b[np * 2 + 0][0] = r0; b[np * 2 + 1][0] = r1;
                b[np * 2 + 0][1] = r2; b[np * 2 + 1][1] = r3;
            }
            #pragma unroll
            for (int mi = 0; mi < 4; mi++)
                #pragma unroll
                for (int ni = 0; ni < 4; ni++)
                    MMA16816(acc[mi][ni][0], acc[mi][ni][1], acc[mi][ni][2], acc[mi][ni][3],
                             a[mi][0], a[mi][1], a[mi][2], a[mi][3], b[ni][0], b[ni][1]);
        }
    }
}

// ---------------- helpers --------------------------------------------------------

__global__ void convert_x_kernel(const float* __restrict__ x, __half* __restrict__ xh) {
    size_t i = ((size_t)blockIdx.x * blockDim.x + threadIdx.x) * 4;
    float4 v = *(const float4*)(x + i);
    union { __half2 h[2]; uint2 u; } w;
    w.h[0] = __floats2half2_rn(v.x, v.y);
    w.h[1] = __floats2half2_rn(v.z, v.w);
    *(uint2*)(xh + i) = w.u;
}

// skew (8192 blocks) + row_sum (2048 blocks), one launch
__global__ void prep_kernel(const float* __restrict__ W1, const float* __restrict__ W2,
                            __half* __restrict__ Ah, __half* __restrict__ Bneg,
                            float* __restrict__ part) {
    int bid = blockIdx.x;
    if (bid < 8192) {
        int gidx = bid * 256 + threadIdx.x;
        int z = gidx >> 20;
        int idx = gidx & (DD - 1);
        const float* W = z ? W2 : W1;
        int i = idx >> 10, j = idx & (D - 1);
        float a = 5.0f * (W[idx] - W[j * D + i]);   // 10 * 0.5 * (W - W^T)
        Ah[gidx]   = __float2half(a);
        Bneg[gidx] = __float2half(-a);
    } else {
        int b = bid - 8192;
        const float* src = (b < D) ? (W1 + (size_t)b * D) : (W2 + (size_t)(b - D) * D);
        __shared__ float sm[256];
        float s = 0.f;
        for (int j = threadIdx.x; j < D; j += 256) s += src[j];
        sm[threadIdx.x] = s;
        __syncthreads();
        for (int o = 128; o > 0; o >>= 1) {
            if (threadIdx.x < o) sm[threadIdx.x] += sm[threadIdx.x + o];
            __syncthreads();
        }
        if (threadIdx.x == 0) part[b] = sm[0];
    }
}

__global__ void pass_kernel(const float* __restrict__ part,
                            const float* __restrict__ theta,
                            float* __restrict__ out) {
    __shared__ float sm[1024];
    sm[threadIdx.x] = part[threadIdx.x] + part[threadIdx.x + 1024];
    __syncthreads();
    for (int o = 512; o > 0; o >>= 1) {
        if (threadIdx.x < o) sm[threadIdx.x] += sm[threadIdx.x + o];
        __syncthreads();
    }
    if (threadIdx.x == 0)
        out[0] = (sm[0] / 1048576.0f + theta[0]) * 1e-6f;
}

// ---------------- chain stage 1:  C = a @ (-a)^T = a^2  -------------------------
// epilogue: P2 = half(C), ET = half(0.1C - a)
__global__ void __launch_bounds__(256, 2)
chain1_kernel(const __half* __restrict__ Ah, const __half* __restrict__ Bneg,
              __half* __restrict__ P2, __half* __restrict__ ET)
{
    extern __shared__ char dsm_raw[];
    char* dsm = (char*)(((uintptr_t)dsm_raw + 1023) & ~(uintptr_t)1023);
    GemmCtx cx = make_ctx(smem_u32(dsm));
    const size_t loff = (size_t)blockIdx.z * DD;
    const size_t rowBase = (size_t)blockIdx.y * 128;
    const int    colBase = blockIdx.x * 128;

    float acc[4][4][4];
    gemm_main(cx, Ah + loff, Bneg + loff, rowBase, colBase, acc);

    const __half* Aeo = Ah + loff;
    __half* P2o = P2 + loff;
    __half* ETo = ET + loff;
    #pragma unroll
    for (int mi = 0; mi < 4; mi++) {
        const int rloc = cx.wr * 64 + mi * 16 + cx.grp;
        #pragma unroll
        for (int rr = 0; rr < 2; rr++) {
            const size_t grow = rowBase + rloc + rr * 8;
            #pragma unroll
            for (int ni = 0; ni < 4; ni++) {
                const int gcol = colBase + cx.wc * 32 + ni * 8 + cx.q * 2;
                float v0 = acc[mi][ni][rr * 2 + 0];
                float v1 = acc[mi][ni][rr * 2 + 1];
                const size_t idx = grow * D + gcol;
                *(__half2*)&P2o[idx] = __floats2half2_rn(v0, v1);
                __half2 a2 = *(const __half2*)&Aeo[idx];
                *(__half2*)&ETo[idx] = __floats2half2_rn(0.1f * v0 - __low2float(a2),
                                                         0.1f * v1 - __high2float(a2));
            }
        }
    }
}

// ---------------- chain stage 2:  C = P2 @ ET^T = a^3 + 0.1 a^4 -----------------
// epilogue (fused combine): M = half(0.2 a + 0.02 P2 + 2e-3 C)
__global__ void __launch_bounds__(256, 2)
chain2_kernel(const __half* __restrict__ P2, const __half* __restrict__ ET,
              const __half* __restrict__ Ah, __half* __restrict__ M)
{
    extern __shared__ char dsm_raw[];
    char* dsm = (char*)(((uintptr_t)dsm_raw + 1023) & ~(uintptr_t)1023);
    GemmCtx cx = make_ctx(smem_u32(dsm));
    const size_t loff = (size_t)blockIdx.z * DD;
    const size_t rowBase = (size_t)blockIdx.y * 128;
    const int    colBase = blockIdx.x * 128;

    float acc[4][4][4];
    gemm_main(cx, P2 + loff, ET + loff, rowBase, colBase, acc);

    const __half* Aeo  = Ah + loff;
    const __half* P2o  = P2 + loff;
    __half* Mo = M + loff;
    #pragma unroll
    for (int mi = 0; mi < 4; mi++) {
        const int rloc = cx.wr * 64 + mi * 16 + cx.grp;
        #pragma unroll
        for (int rr = 0; rr < 2; rr++) {
            const size_t grow = rowBase + rloc + rr * 8;
            #pragma unroll
            for (int ni = 0; ni < 4; ni++) {
                const int gcol = colBase + cx.wc * 32 + ni * 8 + cx.q * 2;
                const size_t idx = grow * D + gcol;
                float2 a2  = __half22float2(*(const __half2*)&Aeo[idx]);
                float2 p2  = __half22float2(*(const __half2*)&P2o[idx]);
                float m0 = 0.2f * a2.x + 0.02f * p2.x + 2e-3f * acc[mi][ni][rr * 2 + 0];
                float m1 = 0.2f * a2.y + 0.02f * p2.y + 2e-3f * acc[mi][ni][rr * 2 + 1];
                *(__half2*)&Mo[idx] = __floats2half2_rn(m0, m1);
            }
        }
    }
}

// ---------------- rotW:  Wa = Rot (I + M1),  WaT = Wa^T -------------------------
__global__ void rotw_kernel(const __half* __restrict__ M1,
                            const float* __restrict__ theta,
                            __half* __restrict__ Wa, __half* __restrict__ WaT)
{
    __shared__ __half tile[64][65];
    float th = theta[0];
    float c = cosf(th), s = sinf(th);
    const int r0 = blockIdx.y * 64, c0 = blockIdx.x * 64;
    const int tid = threadIdx.x;
    #pragma unroll
    for (int i = 0; i < 16; i++) {
        int idx = tid + (i << 8);
        int r = idx >> 6, cc = idx & 63;
        int gr = r0 + r, gc = c0 + cc;
        int gp = gr ^ 1;
        float xr = __half2float(M1[(size_t)gr * D + gc]) + (gr == gc ? 1.f : 0.f);
        float xp = __half2float(M1[(size_t)gp * D + gc]) + (gp == gc ? 1.f : 0.f);
        float wa = (gr & 1) ? (c * xr + s * xp) : (c * xr - s * xp);
        __half h = __float2half(wa);
        Wa[(size_t)gr * D + gc] = h;
        tile[r][cc] = h;
    }
    __syncthreads();
    #pragma unroll
    for (int i = 0; i < 16; i++) {
        int idx = tid + (i << 8);
        int tr = idx >> 6, tc = idx & 63;
        WaT[(size_t)(c0 + tr) * D + (r0 + tc)] = tile[tc][tr];
    }
}

// ---------------- buildW:  C = M2 @ WaT^T = M2 @ Wa;  W = half(Wa + C) ----------
__global__ void __launch_bounds__(256, 2)
buildw_kernel(const __half* __restrict__ M2, const __half* __restrict__ WaT,
              const __half* __restrict__ Wa, __half* __restrict__ W)
{
    extern __shared__ char dsm_raw[];
    char* dsm = (char*)(((uintptr_t)dsm_raw + 1023) & ~(uintptr_t)1023);
    GemmCtx cx = make_ctx(smem_u32(dsm));
    const size_t rowBase = (size_t)blockIdx.y * 128;
    const int    colBase = blockIdx.x * 128;

    float acc[4][4][4];
    gemm_main(cx, M2, WaT, rowBase, colBase, acc);

    #pragma unroll
    for (int mi = 0; mi < 4; mi++) {
        const int rloc = cx.wr * 64 + mi * 16 + cx.grp;
        #pragma unroll
        for (int rr = 0; rr < 2; rr++) {
            const size_t grow = rowBase + rloc + rr * 8;
            #pragma unroll
            for (int ni = 0; ni < 4; ni++) {
                const int gcol = colBase + cx.wc * 32 + ni * 8 + cx.q * 2;
                const size_t idx = grow * D + gcol;
                float2 wv = __half22float2(*(const __half2*)&Wa[idx]);
                *(__half2*)&W[idx] = __floats2half2_rn(wv.x + acc[mi][ni][rr * 2 + 0],
                                                       wv.y + acc[mi][ni][rr * 2 + 1]);
            }
        }
    }
}

// ---------------- the ONE big GEMM (64x64 warp tile, 128 threads) ---------------
// out = xh @ W^T + pass
__global__ void __launch_bounds__(128, 2)
bigw_kernel(const __half* __restrict__ xh, const __half* __restrict__ W,
            const float* __restrict__ passv, float* __restrict__ out)
{
    extern __shared__ char dsm_raw[];
    char* dsm = (char*)(((uintptr_t)dsm_raw + 1023) & ~(uintptr_t)1023);
    const uint32_t sbase = smem_u32(dsm);

    const int tid  = threadIdx.x;
    const int w    = tid >> 5, lane = tid & 31;
    const int wr = w >> 1, wc = w & 1;            // 2x2 warp grid, 64x64 each
    const int grp = lane >> 2, q = lane & 3;
    const int lrow = lane & 15, lk = lane >> 4;

    const size_t rowBase = (size_t)blockIdx.y * 128;
    const int    colBase = blockIdx.x * 128;

    float acc[4][8][4];
    #pragma unroll
    for (int a = 0; a < 4; a++)
        #pragma unroll
        for (int b = 0; b < 8; b++)
            #pragma unroll
            for (int c = 0; c < 4; c++) acc[a][b][c] = 0.f;

    auto load_tile = [&](int kt) {
        const int stage = kt % 3;
        const int k0 = kt * TBK;
        #pragma unroll
        for (int i = 0; i < 16; i++) {
            int id  = tid + (i << 7);              // 128 threads x 16 = 2048 chunks
            int isB = id >> 10;
            int rc  = id & 1023;
            int row = rc >> 3, c = rc & 7;
            uint32_t sw = ((uint32_t)row << 7) | (((uint32_t)(c ^ (row & 7))) << 4);
            const __half* g = (isB ? (W  + (size_t)(colBase + row) * D)
                                   : (xh + (rowBase + row) * (size_t)D)) + k0 + (c << 3);
            uint32_t s = sbase + stage * STAGEB + (isB << 14) + sw;
            asm volatile("cp.async.cg.shared.global [%0], [%1], 16;\n" :: "r"(s), "l"(g));
        }
        asm volatile("cp.async.commit_group;\n");
    };

    load_tile(0);
    load_tile(1);

    for (int kt = 0; kt < KT; kt++) {
        if (kt == KT - 1) asm volatile("cp.async.wait_group 0;\n");
        else              asm volatile("cp.async.wait_group 1;\n");
        __syncthreads();
        if (kt + 2 < KT) load_tile(kt + 2);

        const uint32_t aS = sbase + (kt % 3) * STAGEB;
        const uint32_t bS = aS + 16384;

        #pragma unroll
        for (int kp = 0; kp < 4; kp++) {
            const uint32_t ch = (uint32_t)(kp * 2 + lk);
            uint32_t a[4][4];
            #pragma unroll
            for (int mi = 0; mi < 4; mi++) {
                int row = wr * 64 + mi * 16 + lrow;
                uint32_t ad = aS + ((uint32_t)row << 7) + ((ch ^ (uint32_t)(row & 7)) << 4);
                LDSM_X4(a[mi][0], a[mi][1], a[mi][2], a[mi][3], ad);
            }
            uint32_t b[8][2];
            #pragma unroll
            for (int np = 0; np < 4; np++) {
                int row = wc * 64 + np * 16 + lrow;
                uint32_t bd = bS + ((uint32_t)row << 7) + ((ch ^ (uint32_t)(row & 7)) << 4);
                uint32_t r0, r1, r2, r3;
                LDSM_X4(r0, r1, r2, r3, bd);
                b[np * 2 + 0][0] = r0; b[np * 2 + 1][0] = r1;
                b[np * 2 + 0][1] = r2; b[np * 2 + 1][1] = r3;
            }
            #pragma unroll
            for (int mi = 0; mi < 4; mi++)
                #pragma unroll
                for (int ni = 0; ni < 8; ni++)
                    MMA16816(acc[mi][ni][0], acc[mi][ni][1], acc[mi][ni][2], acc[mi][ni][3],
                             a[mi][0], a[mi][1], a[mi][2], a[mi][3], b[ni][0], b[ni][1]);
        }
    }

    const float pv = passv[0];
    #pragma unroll
    for (int mi = 0; mi < 4; mi++) {
        const int rloc = wr * 64 + mi * 16 + grp;
        #pragma unroll
        for (int rr = 0; rr < 2; rr++) {
            const size_t grow = rowBase + rloc + rr * 8;
            #pragma unroll
            for (int ni = 0; ni < 8; ni++) {
                const int gcol = colBase + wc * 64 + ni * 8 + q * 2;
                const size_t idx = grow * D + gcol;
                float2 o;
                o.x = acc[mi][ni][rr * 2 + 0] + pv;
                o.y = acc[mi][ni][rr * 2 + 1] + pv;
                *(float2*)&out[idx] = o;
            }
        }
    }
}

// ---------------- host launcher (fork/join graph branches) ----------------------

extern "C" void kernel_launch(void* const* d_in, const int* in_sizes, int n_in,
                              void* d_out, int out_size) {
    const float* x     = (const float*)d_in[0];
    const float* u1    = (const float*)d_in[1];
    const float* u2    = (const float*)d_in[2];
    const float* theta = (const float*)d_in[3];
    float* out = (float*)d_out;

    __half *xh, *Ah, *Bneg, *P2, *ET, *M, *Wa, *WaT, *W;
    float *part, *pass;
    cudaGetSymbolAddress((void**)&xh,   g_xh);
    cudaGetSymbolAddress((void**)&Ah,   g_Ah);
    cudaGetSymbolAddress((void**)&Bneg, g_Bneg);
    cudaGetSymbolAddress((void**)&P2,   g_P2);
    cudaGetSymbolAddress((void**)&ET,   g_ET);
    cudaGetSymbolAddress((void**)&M,    g_M);
    cudaGetSymbolAddress((void**)&Wa,   g_Wa);
    cudaGetSymbolAddress((void**)&WaT,  g_WaT);
    cudaGetSymbolAddress((void**)&W,    g_W);
    cudaGetSymbolAddress((void**)&part, g_part);
    cudaGetSymbolAddress((void**)&pass, g_pass);

    cudaFuncSetAttribute(chain1_kernel, cudaFuncAttributeMaxDynamicSharedMemorySize, SMEMSZ);
    cudaFuncSetAttribute(chain2_kernel, cudaFuncAttributeMaxDynamicSharedMemorySize, SMEMSZ);
    cudaFuncSetAttribute(buildw_kernel, cudaFuncAttributeMaxDynamicSharedMemorySize, SMEMSZ);
    cudaFuncSetAttribute(bigw_kernel,   cudaFuncAttributeMaxDynamicSharedMemorySize, SMEMSZ);

    // Side stream + events for a parallel graph branch (created per call,
    // intentionally not destroyed: destroying a stream participating in an
    // active capture is illegal; handles are host-side only).
    cudaStream_t sB;
    cudaEvent_t evFork, evJoin;
    cudaStreamCreateWithFlags(&sB, cudaStreamNonBlocking);
    cudaEventCreateWithFlags(&evFork, cudaEventDisableTiming);
    cudaEventCreateWithFlags(&evJoin, cudaEventDisableTiming);

    // fork: branch B (convert_x) runs concurrently with the weight chain
    cudaEventRecord(evFork, 0);
    cudaStreamWaitEvent(sB, evFork, 0);
    convert_x_kernel<<<(int)(((size_t)NROWS * D) / 4 / 256), 256, 0, sB>>>(x, xh);
    cudaEventRecord(evJoin, sB);

    // branch A (default stream): weight chain
    prep_kernel<<<8192 + 2048, 256>>>(u1, u2, Ah, Bneg, part);
    pass_kernel<<<1, 1024>>>(part, theta, pass);
    chain1_kernel<<<dim3(8, 8, 2), 256, SMEMSZ>>>(Ah, Bneg, P2, ET);
    chain2_kernel<<<dim3(8, 8, 2), 256, SMEMSZ>>>(P2, ET, Ah, M);
    rotw_kernel<<<dim3(16, 16), 256>>>(M, theta, Wa, WaT);
    buildw_kernel<<<dim3(8, 8), 256, SMEMSZ>>>(M + DD, WaT, Wa, W);

    // join, then the ONE big GEMM
    cudaStreamWaitEvent(0, evJoin, 0);
    bigw_kernel<<<dim3(D / 128, NROWS / 128), 128, SMEMSZ>>>(xh, W, pass, out);
}

// round 15
// speedup vs baseline: 1.0116x; 1.0116x over previous
#include <cuda_runtime.h>
#include <cuda_fp16.h>
#include <stdint.h>

#define D      1024
#define NROWS  65536
#define DD     (D * D)

// GEMM tile: 128x128, BK=64, 3-stage cp.async, ldmatrix + XOR swizzle
#define TBK     64
#define KT      (D / TBK)        // 16
#define STAGEB  32768            // (128 rows A + 128 rows B) * 64 halves * 2B
#define SMEMSZ  (3 * STAGEB + 1024)

// ---------------- scratch (static device globals; ALL 256B-aligned) ------------
__device__ __align__(256) __half g_xh[(size_t)NROWS * D];
__device__ __align__(256) __half g_Ah  [2 * DD];   // a = 10A
__device__ __align__(256) __half g_Bneg[2 * DD];   // -a
__device__ __align__(256) __half g_P2[2 * DD];     // a^2
__device__ __align__(256) __half g_ET[2 * DD];     // E^T = 0.1 a^2 - a
__device__ __align__(256) __half g_M [2 * DD];     // M1 | M2  (U = I + M)
__device__ __align__(256) __half g_Wa [DD];        // Rot (I + M1)
__device__ __align__(256) __half g_WaT[DD];        // Wa^T
__device__ __align__(256) __half g_W  [DD];        // U2 Rot U1
__device__ __align__(256) float  g_part[2 * D];
__device__ __align__(256) float  g_pass[1];

__device__ __forceinline__ uint32_t smem_u32(const void* p) {
    return (uint32_t)__cvta_generic_to_shared(p);
}
#define LDSM_X4(r0, r1, r2, r3, addr) \
    asm volatile("ldmatrix.sync.aligned.m8n8.x4.shared.b16 {%0,%1,%2,%3}, [%4];" \
                 : "=r"(r0), "=r"(r1), "=r"(r2), "=r"(r3) : "r"(addr))
#define MMA16816(c0,c1,c2,c3,a0,a1,a2,a3,b0,b1) \
    asm volatile("mma.sync.aligned.m16n8k16.row.col.f32.f16.f16.f32 " \
        "{%0,%1,%2,%3}, {%4,%5,%6,%7}, {%8,%9}, {%0,%1,%2,%3};\n" \
        : "+f"(c0), "+f"(c1), "+f"(c2), "+f"(c3) \
        : "r"(a0), "r"(a1), "r"(a2), "r"(a3), "r"(b0), "r"(b1))

// ================= GEMM mainloop (64x32 warp tile, 256 threads) ==================
struct GemmCtx {
    uint32_t sbase;
    int tid, wr, wc, grp, q, lrow, lk;
};

__device__ __forceinline__ GemmCtx make_ctx(uint32_t sbase) {
    GemmCtx cx;
    cx.sbase = sbase;
    cx.tid = threadIdx.x;
    int w = cx.tid >> 5, lane = cx.tid & 31;
    cx.wr = w >> 2; cx.wc = w & 3;
    cx.grp = lane >> 2; cx.q = lane & 3;
    cx.lrow = lane & 15; cx.lk = lane >> 4;
    return cx;
}

__device__ __forceinline__ void gemm_main(const GemmCtx& cx,
                                          const __half* __restrict__ A,
                                          const __half* __restrict__ B,
                                          size_t rowBase, int colBase,
                                          float acc[4][4][4])
{
    #pragma unroll
    for (int a = 0; a < 4; a++)
        #pragma unroll
        for (int b = 0; b < 4; b++)
            #pragma unroll
            for (int c = 0; c < 4; c++) acc[a][b][c] = 0.f;

    auto load_tile = [&](int kt) {
        const int stage = kt % 3;
        const int k0 = kt * TBK;
        #pragma unroll
        for (int i = 0; i < 8; i++) {
            int id  = cx.tid + (i << 8);
            int isB = id >> 10;
            int rc  = id & 1023;
            int row = rc >> 3, c = rc & 7;
            uint32_t sw = ((uint32_t)row << 7) | (((uint32_t)(c ^ (row & 7))) << 4);
            const __half* g = (isB ? (B + (size_t)(colBase + row) * D)
                                   : (A + (rowBase + row) * (size_t)D)) + k0 + (c << 3);
            uint32_t s = cx.sbase + stage * STAGEB + (isB << 14) + sw;
            asm volatile("cp.async.cg.shared.global [%0], [%1], 16;\n" :: "r"(s), "l"(g));
        }
        asm volatile("cp.async.commit_group;\n");
    };

    load_tile(0);
    load_tile(1);

    for (int kt = 0; kt < KT; kt++) {
        if (kt == KT - 1) asm volatile("cp.async.wait_group 0;\n");
        else              asm volatile("cp.async.wait_group 1;\n");
        __syncthreads();
        if (kt + 2 < KT) load_tile(kt + 2);

        const uint32_t aS = cx.sbase + (kt % 3) * STAGEB;
        const uint32_t bS = aS + 16384;

        #pragma unroll
        for (int kp = 0; kp < 4; kp++) {
            const uint32_t ch = (uint32_t)(kp * 2 + cx.lk);
            uint32_t a[4][4];
            #pragma unroll
            for (int mi = 0; mi < 4; mi++) {
                int row = cx.wr * 64 + mi * 16 + cx.lrow;
                uint32_t ad = aS + ((uint32_t)row << 7) + ((ch ^ (uint32_t)(row & 7)) << 4);
                LDSM_X4(a[mi][0], a[mi][1], a[mi][2], a[mi][3], ad);
            }
            uint32_t b[4][2];
            #pragma unroll
            for (int np = 0; np < 2; np++) {
                int row = cx.wc * 32 + np * 16 + cx.lrow;
                uint32_t bd = bS + ((uint32_t)row << 7) + ((ch ^ (uint32_t)(row & 7)) << 4);
                uint32_t r0, r1, r2, r3;
                LDSM_X4(r0, r1, r2, r3, bd);
                b[np * 2 + 0][0] = r0; b[np * 2 + 1][0] = r1;
                b[np * 2 + 0][1] = r2; b[np * 2 + 1][1] = r3;
            }
            #pragma unroll
            for (int mi = 0; mi < 4; mi++)
                #pragma unroll
                for (int ni = 0; ni < 4; ni++)
                    MMA16816(acc[mi][ni][0], acc[mi][ni][1], acc[mi][ni][2], acc[mi][ni][3],
                             a[mi][0], a[mi][1], a[mi][2], a[mi][3], b[ni][0], b[ni][1]);
        }
    }
}

// ---------------- helpers --------------------------------------------------------

__global__ void convert_x_kernel(const float* __restrict__ x, __half* __restrict__ xh) {
    size_t i = ((size_t)blockIdx.x * blockDim.x + threadIdx.x) * 4;
    float4 v = *(const float4*)(x + i);
    union { __half2 h[2]; uint2 u; } w;
    w.h[0] = __floats2half2_rn(v.x, v.y);
    w.h[1] = __floats2half2_rn(v.z, v.w);
    *(uint2*)(xh + i) = w.u;
}

// skew (8192 blocks) + row_sum (2048 blocks), one launch
__global__ void prep_kernel(const float* __restrict__ W1, const float* __restrict__ W2,
                            __half* __restrict__ Ah, __half* __restrict__ Bneg,
                            float* __restrict__ part) {
    int bid = blockIdx.x;
    if (bid < 8192) {
        int gidx = bid * 256 + threadIdx.x;
        int z = gidx >> 20;
        int idx = gidx & (DD - 1);
        const float* W = z ? W2 : W1;
        int i = idx >> 10, j = idx & (D - 1);
        float a = 5.0f * (W[idx] - W[j * D + i]);   // 10 * 0.5 * (W - W^T)
        Ah[gidx]   = __float2half(a);
        Bneg[gidx] = __float2half(-a);
    } else {
        int b = bid - 8192;
        const float* src = (b < D) ? (W1 + (size_t)b * D) : (W2 + (size_t)(b - D) * D);
        __shared__ float sm[256];
        float s = 0.f;
        for (int j = threadIdx.x; j < D; j += 256) s += src[j];
        sm[threadIdx.x] = s;
        __syncthreads();
        for (int o = 128; o > 0; o >>= 1) {
            if (threadIdx.x < o) sm[threadIdx.x] += sm[threadIdx.x + o];
            __syncthreads();
        }
        if (threadIdx.x == 0) part[b] = sm[0];
    }
}

__global__ void pass_kernel(const float* __restrict__ part,
                            const float* __restrict__ theta,
                            float* __restrict__ out) {
    __shared__ float sm[1024];
    sm[threadIdx.x] = part[threadIdx.x] + part[threadIdx.x + 1024];
    __syncthreads();
    for (int o = 512; o > 0; o >>= 1) {
        if (threadIdx.x < o) sm[threadIdx.x] += sm[threadIdx.x + o];
        __syncthreads();
    }
    if (threadIdx.x == 0)
        out[0] = (sm[0] / 1048576.0f + theta[0]) * 1e-6f;
}

// ---------------- chain stage 1:  C = a @ (-a)^T = a^2  -------------------------
__global__ void __launch_bounds__(256, 2)
chain1_kernel(const __half* __restrict__ Ah, const __half* __restrict__ Bneg,
              __half* __restrict__ P2, __half* __restrict__ ET)
{
    extern __shared__ char dsm_raw[];
    char* dsm = (char*)(((uintptr_t)dsm_raw + 1023) & ~(uintptr_t)1023);
    GemmCtx cx = make_ctx(smem_u32(dsm));
    const size_t loff = (size_t)blockIdx.z * DD;
    const size_t rowBase = (size_t)blockIdx.y * 128;
    const int    colBase = blockIdx.x * 128;

    float acc[4][4][4];
    gemm_main(cx, Ah + loff, Bneg + loff, rowBase, colBase, acc);

    const __half* Aeo = Ah + loff;
    __half* P2o = P2 + loff;
    __half* ETo = ET + loff;
    #pragma unroll
    for (int mi = 0; mi < 4; mi++) {
        const int rloc = cx.wr * 64 + mi * 16 + cx.grp;
        #pragma unroll
        for (int rr = 0; rr < 2; rr++) {
            const size_t grow = rowBase + rloc + rr * 8;
            #pragma unroll
            for (int ni = 0; ni < 4; ni++) {
                const int gcol = colBase + cx.wc * 32 + ni * 8 + cx.q * 2;
                float v0 = acc[mi][ni][rr * 2 + 0];
                float v1 = acc[mi][ni][rr * 2 + 1];
                const size_t idx = grow * D + gcol;
                *(__half2*)&P2o[idx] = __floats2half2_rn(v0, v1);
                __half2 a2 = *(const __half2*)&Aeo[idx];
                *(__half2*)&ETo[idx] = __floats2half2_rn(0.1f * v0 - __low2float(a2),
                                                         0.1f * v1 - __high2float(a2));
            }
        }
    }
}

// ---------------- chain stage 2:  C = P2 @ ET^T = a^3 + 0.1 a^4 -----------------
__global__ void __launch_bounds__(256, 2)
chain2_kernel(const __half* __restrict__ P2, const __half* __restrict__ ET,
              const __half* __restrict__ Ah, __half* __restrict__ M)
{
    extern __shared__ char dsm_raw[];
    char* dsm = (char*)(((uintptr_t)dsm_raw + 1023) & ~(uintptr_t)1023);
    GemmCtx cx = make_ctx(smem_u32(dsm));
    const size_t loff = (size_t)blockIdx.z * DD;
    const size_t rowBase = (size_t)blockIdx.y * 128;
    const int    colBase = blockIdx.x * 128;

    float acc[4][4][4];
    gemm_main(cx, P2 + loff, ET + loff, rowBase, colBase, acc);

    const __half* Aeo  = Ah + loff;
    const __half* P2o  = P2 + loff;
    __half* Mo = M + loff;
    #pragma unroll
    for (int mi = 0; mi < 4; mi++) {
        const int rloc = cx.wr * 64 + mi * 16 + cx.grp;
        #pragma unroll
        for (int rr = 0; rr < 2; rr++) {
            const size_t grow = rowBase + rloc + rr * 8;
            #pragma unroll
            for (int ni = 0; ni < 4; ni++) {
                const int gcol = colBase + cx.wc * 32 + ni * 8 + cx.q * 2;
                const size_t idx = grow * D + gcol;
                float2 a2  = __half22float2(*(const __half2*)&Aeo[idx]);
                float2 p2  = __half22float2(*(const __half2*)&P2o[idx]);
                float m0 = 0.2f * a2.x + 0.02f * p2.x + 2e-3f * acc[mi][ni][rr * 2 + 0];
                float m1 = 0.2f * a2.y + 0.02f * p2.y + 2e-3f * acc[mi][ni][rr * 2 + 1];
                *(__half2*)&Mo[idx] = __floats2half2_rn(m0, m1);
            }
        }
    }
}

// ---------------- rotW:  Wa = Rot (I + M1),  WaT = Wa^T -------------------------
__global__ void rotw_kernel(const __half* __restrict__ M1,
                            const float* __restrict__ theta,
                            __half* __restrict__ Wa, __half* __restrict__ WaT)
{
    __shared__ __half tile[64][65];
    float th = theta[0];
    float c = cosf(th), s = sinf(th);
    const int r0 = blockIdx.y * 64, c0 = blockIdx.x * 64;
    const int tid = threadIdx.x;
    #pragma unroll
    for (int i = 0; i < 16; i++) {
        int idx = tid + (i << 8);
        int r = idx >> 6, cc = idx & 63;
        int gr = r0 + r, gc = c0 + cc;
        int gp = gr ^ 1;
        float xr = __half2float(M1[(size_t)gr * D + gc]) + (gr == gc ? 1.f : 0.f);
        float xp = __half2float(M1[(size_t)gp * D + gc]) + (gp == gc ? 1.f : 0.f);
        float wa = (gr & 1) ? (c * xr + s * xp) : (c * xr - s * xp);
        __half h = __float2half(wa);
        Wa[(size_t)gr * D + gc] = h;
        tile[r][cc] = h;
    }
    __syncthreads();
    #pragma unroll
    for (int i = 0; i < 16; i++) {
        int idx = tid + (i << 8);
        int tr = idx >> 6, tc = idx & 63;
        WaT[(size_t)(c0 + tr) * D + (r0 + tc)] = tile[tc][tr];
    }
}

// ---------------- buildW:  C = M2 @ WaT^T = M2 @ Wa;  W = half(Wa + C) ----------
__global__ void __launch_bounds__(256, 2)
buildw_kernel(const __half* __restrict__ M2, const __half* __restrict__ WaT,
              const __half* __restrict__ Wa, __half* __restrict__ W)
{
    extern __shared__ char dsm_raw[];
    char* dsm = (char*)(((uintptr_t)dsm_raw + 1023) & ~(uintptr_t)1023);
    GemmCtx cx = make_ctx(smem_u32(dsm));
    const size_t rowBase = (size_t)blockIdx.y * 128;
    const int    colBase = blockIdx.x * 128;

    float acc[4][4][4];
    gemm_main(cx, M2, WaT, rowBase, colBase, acc);

    #pragma unroll
    for (int mi = 0; mi < 4; mi++) {
        const int rloc = cx.wr * 64 + mi * 16 + cx.grp;
        #pragma unroll
        for (int rr = 0; rr < 2; rr++) {
            const size_t grow = rowBase + rloc + rr * 8;
            #pragma unroll
            for (int ni = 0; ni < 4; ni++) {
                const int gcol = colBase + cx.wc * 32 + ni * 8 + cx.q * 2;
                const size_t idx = grow * D + gcol;
                float2 wv = __half22float2(*(const __half2*)&Wa[idx]);
                *(__half2*)&W[idx] = __floats2half2_rn(wv.x + acc[mi][ni][rr * 2 + 0],
                                                       wv.y + acc[mi][ni][rr * 2 + 1]);
            }
        }
    }
}

// ---------------- the ONE big GEMM (64x64 warp tile, 128 threads) ---------------
// out = xh @ W^T + pass      (fragment-pipelined inner loop)
__global__ void __launch_bounds__(128, 2)
bigw_kernel(const __half* __restrict__ xh, const __half* __restrict__ W,
            const float* __restrict__ passv, float* __restrict__ out)
{
    extern __shared__ char dsm_raw[];
    char* dsm = (char*)(((uintptr_t)dsm_raw + 1023) & ~(uintptr_t)1023);
    const uint32_t sbase = smem_u32(dsm);

    const int tid  = threadIdx.x;
    const int w    = tid >> 5, lane = tid & 31;
    const int wr = w >> 1, wc = w & 1;            // 2x2 warp grid, 64x64 each
    const int grp = lane >> 2, q = lane & 3;
    const int lrow = lane & 15, lk = lane >> 4;

    const size_t rowBase = (size_t)blockIdx.y * 128;
    const int    colBase = blockIdx.x * 128;

    float acc[4][8][4];
    #pragma unroll
    for (int a = 0; a < 4; a++)
        #pragma unroll
        for (int b = 0; b < 8; b++)
            #pragma unroll
            for (int c = 0; c < 4; c++) acc[a][b][c] = 0.f;

    auto load_tile = [&](int kt) {
        const int stage = kt % 3;
        const int k0 = kt * TBK;
        #pragma unroll
        for (int i = 0; i < 16; i++) {
            int id  = tid + (i << 7);              // 128 threads x 16 = 2048 chunks
            int isB = id >> 10;
            int rc  = id & 1023;
            int row = rc >> 3, c = rc & 7;
            uint32_t sw = ((uint32_t)row << 7) | (((uint32_t)(c ^ (row & 7))) << 4);
            const __half* g = (isB ? (W  + (size_t)(colBase + row) * D)
                                   : (xh + (rowBase + row) * (size_t)D)) + k0 + (c << 3);
            uint32_t s = sbase + stage * STAGEB + (isB << 14) + sw;
            asm volatile("cp.async.cg.shared.global [%0], [%1], 16;\n" :: "r"(s), "l"(g));
        }
        asm volatile("cp.async.commit_group;\n");
    };

    load_tile(0);
    load_tile(1);

    uint32_t af[2][4][4];
    uint32_t bf[2][8][2];

    auto load_frags = [&](uint32_t aS, uint32_t bS, int kp, int buf) {
        const uint32_t ch = (uint32_t)(kp * 2 + lk);
        #pragma unroll
        for (int mi = 0; mi < 4; mi++) {
            int row = wr * 64 + mi * 16 + lrow;
            uint32_t ad = aS + ((uint32_t)row << 7) + ((ch ^ (uint32_t)(row & 7)) << 4);
            LDSM_X4(af[buf][mi][0], af[buf][mi][1], af[buf][mi][2], af[buf][mi][3], ad);
        }
        #pragma unroll
        for (int np = 0; np < 4; np++) {
            int row = wc * 64 + np * 16 + lrow;
            uint32_t bd = bS + ((uint32_t)row << 7) + ((ch ^ (uint32_t)(row & 7)) << 4);
            uint32_t r0, r1, r2, r3;
            LDSM_X4(r0, r1, r2, r3, bd);
            bf[buf][np * 2 + 0][0] = r0; bf[buf][np * 2 + 1][0] = r1;
            bf[buf][np * 2 + 0][1] = r2; bf[buf][np * 2 + 1][1] = r3;
        }
    };

    for (int kt = 0; kt < KT; kt++) {
        if (kt == KT - 1) asm volatile("cp.async.wait_group 0;\n");
        else              asm volatile("cp.async.wait_group 1;\n");
        __syncthreads();
        if (kt + 2 < KT) load_tile(kt + 2);

        const uint32_t aS = sbase + (kt % 3) * STAGEB;
        const uint32_t bS = aS + 16384;

        load_frags(aS, bS, 0, 0);
        #pragma unroll
        for (int kp = 0; kp < 4; kp++) {
            const int cur = kp & 1;
            if (kp < 3) load_frags(aS, bS, kp + 1, cur ^ 1);
            #pragma unroll
            for (int mi = 0; mi < 4; mi++)
                #pragma unroll
                for (int ni = 0; ni < 8; ni++)
                    MMA16816(acc[mi][ni][0], acc[mi][ni][1], acc[mi][ni][2], acc[mi][ni][3],
                             af[cur][mi][0], af[cur][mi][1], af[cur][mi][2], af[cur][mi][3],
                             bf[cur][ni][0], bf[cur][ni][1]);
        }
    }

    const float pv = passv[0];
    #pragma unroll
    for (int mi = 0; mi < 4; mi++) {
        const int rloc = wr * 64 + mi * 16 + grp;
        #pragma unroll
        for (int rr = 0; rr < 2; rr++) {
            const size_t grow = rowBase + rloc + rr * 8;
            #pragma unroll
            for (int ni = 0; ni < 8; ni++) {
                const int gcol = colBase + wc * 64 + ni * 8 + q * 2;
                const size_t idx = grow * D + gcol;
                float2 o;
                o.x = acc[mi][ni][rr * 2 + 0] + pv;
                o.y = acc[mi][ni][rr * 2 + 1] + pv;
                *(float2*)&out[idx] = o;
            }
        }
    }
}

// ---------------- host launcher ------------------------------------------------

extern "C" void kernel_launch(void* const* d_in, const int* in_sizes, int n_in,
                              void* d_out, int out_size) {
    const float* x     = (const float*)d_in[0];
    const float* u1    = (const float*)d_in[1];
    const float* u2    = (const float*)d_in[2];
    const float* theta = (const float*)d_in[3];
    float* out = (float*)d_out;

    __half *xh, *Ah, *Bneg, *P2, *ET, *M, *Wa, *WaT, *W;
    float *part, *pass;
    cudaGetSymbolAddress((void**)&xh,   g_xh);
    cudaGetSymbolAddress((void**)&Ah,   g_Ah);
    cudaGetSymbolAddress((void**)&Bneg, g_Bneg);
    cudaGetSymbolAddress((void**)&P2,   g_P2);
    cudaGetSymbolAddress((void**)&ET,   g_ET);
    cudaGetSymbolAddress((void**)&M,    g_M);
    cudaGetSymbolAddress((void**)&Wa,   g_Wa);
    cudaGetSymbolAddress((void**)&WaT,  g_WaT);
    cudaGetSymbolAddress((void**)&W,    g_W);
    cudaGetSymbolAddress((void**)&part, g_part);
    cudaGetSymbolAddress((void**)&pass, g_pass);

    cudaFuncSetAttribute(chain1_kernel, cudaFuncAttributeMaxDynamicSharedMemorySize, SMEMSZ);
    cudaFuncSetAttribute(chain2_kernel, cudaFuncAttributeMaxDynamicSharedMemorySize, SMEMSZ);
    cudaFuncSetAttribute(buildw_kernel, cudaFuncAttributeMaxDynamicSharedMemorySize, SMEMSZ);
    cudaFuncSetAttribute(bigw_kernel,   cudaFuncAttributeMaxDynamicSharedMemorySize, SMEMSZ);

    // skew (a = 10A, -a) + row sums
    prep_kernel<<<8192 + 2048, 256>>>(u1, u2, Ah, Bneg, part);
    // passthrough scalar
    pass_kernel<<<1, 1024>>>(part, theta, pass);

    // fp16 inputs
    convert_x_kernel<<<(int)(((size_t)NROWS * D) / 4 / 256), 256>>>(x, xh);

    // Neumann chain (both layers): M = U - I
    chain1_kernel<<<dim3(8, 8, 2), 256, SMEMSZ>>>(Ah, Bneg, P2, ET);
    chain2_kernel<<<dim3(8, 8, 2), 256, SMEMSZ>>>(P2, ET, Ah, M);

    // Wa = Rot (I + M1), WaT = Wa^T
    rotw_kernel<<<dim3(16, 16), 256>>>(M, theta, Wa, WaT);
    // W = (I + M2) Wa = Wa + M2 @ Wa
    buildw_kernel<<<dim3(8, 8), 256, SMEMSZ>>>(M + DD, WaT, Wa, W);

    // out = x @ W^T + passthrough   (the ONE big GEMM, frag-pipelined)
    bigw_kernel<<<dim3(D / 128, NROWS / 128), 128, SMEMSZ>>>(xh, W, pass, out);
}

// round 17
// speedup vs baseline: 1.0280x; 1.0162x over previous
#include <cuda_runtime.h>
#include <cuda_fp16.h>
#include <stdint.h>

#define D      1024
#define NROWS  65536
#define DD     (D * D)

#define TBK     64
#define KT      (D / TBK)        // 16
// big GEMM tile: 128x128
#define STAGEB  32768
#define SMEMSZ  (3 * STAGEB + 1024)
// chain GEMM tile: 128x64
#define CSTAGE  24576            // A 16KB + B 8KB
#define CSMEM   (3 * CSTAGE + 1024)

// ---------------- scratch (static device globals; ALL 256B-aligned) ------------
__device__ __align__(256) __half g_xh[(size_t)NROWS * D];
__device__ __align__(256) __half g_Ah  [2 * DD];   // a = 10A
__device__ __align__(256) __half g_Bneg[2 * DD];   // -a
__device__ __align__(256) __half g_P2[2 * DD];     // a^2
__device__ __align__(256) __half g_ET[2 * DD];     // E^T = 0.1 a^2 - a
__device__ __align__(256) __half g_M [2 * DD];     // M1 | M2  (U = I + M)
__device__ __align__(256) __half g_Wa [DD];        // Rot (I + M1)
__device__ __align__(256) __half g_WaT[DD];        // Wa^T
__device__ __align__(256) __half g_W  [DD];        // U2 Rot U1
__device__ __align__(256) float  g_part[2 * D];
__device__ __align__(256) float  g_pass[1];

__device__ __forceinline__ uint32_t smem_u32(const void* p) {
    return (uint32_t)__cvta_generic_to_shared(p);
}
#define LDSM_X4(r0, r1, r2, r3, addr) \
    asm volatile("ldmatrix.sync.aligned.m8n8.x4.shared.b16 {%0,%1,%2,%3}, [%4];" \
                 : "=r"(r0), "=r"(r1), "=r"(r2), "=r"(r3) : "r"(addr))
#define MMA16816(c0,c1,c2,c3,a0,a1,a2,a3,b0,b1) \
    asm volatile("mma.sync.aligned.m16n8k16.row.col.f32.f16.f16.f32 " \
        "{%0,%1,%2,%3}, {%4,%5,%6,%7}, {%8,%9}, {%0,%1,%2,%3};\n" \
        : "+f"(c0), "+f"(c1), "+f"(c2), "+f"(c3) \
        : "r"(a0), "r"(a1), "r"(a2), "r"(a3), "r"(b0), "r"(b1))

// ================= chain GEMM mainloop: 128x64 tile, 256 threads =================
// warp grid 2x4, warp tile 64x16; acc[4][2][4]
struct ChainCtx {
    uint32_t sbase;
    int tid, wr, wc, grp, q, lrow, lk;
};

__device__ __forceinline__ ChainCtx make_cctx(uint32_t sbase) {
    ChainCtx cx;
    cx.sbase = sbase;
    cx.tid = threadIdx.x;
    int w = cx.tid >> 5, lane = cx.tid & 31;
    cx.wr = w >> 2; cx.wc = w & 3;
    cx.grp = lane >> 2; cx.q = lane & 3;
    cx.lrow = lane & 15; cx.lk = lane >> 4;
    return cx;
}

__device__ __forceinline__ void cgemm_main(const ChainCtx& cx,
                                           const __half* __restrict__ A,
                                           const __half* __restrict__ B,
                                           size_t rowBase, int colBase,
                                           float acc[4][2][4])
{
    #pragma unroll
    for (int a = 0; a < 4; a++)
        #pragma unroll
        for (int b = 0; b < 2; b++)
            #pragma unroll
            for (int c = 0; c < 4; c++) acc[a][b][c] = 0.f;

    auto load_tile = [&](int kt) {
        const int stage = kt % 3;
        const int k0 = kt * TBK;
        #pragma unroll
        for (int i = 0; i < 6; i++) {
            int id  = cx.tid + (i << 8);           // 0..1535 16B chunks
            int isB = (id >= 1024);
            int rc  = isB ? (id - 1024) : id;
            int row = rc >> 3, c = rc & 7;
            uint32_t sw = ((uint32_t)row << 7) | (((uint32_t)(c ^ (row & 7))) << 4);
            const __half* g = (isB ? (B + (size_t)(colBase + row) * D)
                                   : (A + (rowBase + row) * (size_t)D)) + k0 + (c << 3);
            uint32_t s = cx.sbase + stage * CSTAGE + (isB ? 16384u : 0u) + sw;
            asm volatile("cp.async.cg.shared.global [%0], [%1], 16;\n" :: "r"(s), "l"(g));
        }
        asm volatile("cp.async.commit_group;\n");
    };

    load_tile(0);
    load_tile(1);

    for (int kt = 0; kt < KT; kt++) {
        if (kt == KT - 1) asm volatile("cp.async.wait_group 0;\n");
        else              asm volatile("cp.async.wait_group 1;\n");
        __syncthreads();
        if (kt + 2 < KT) load_tile(kt + 2);

        const uint32_t aS = cx.sbase + (kt % 3) * CSTAGE;
        const uint32_t bS = aS + 16384;

        #pragma unroll
        for (int kp = 0; kp < 4; kp++) {
            const uint32_t ch = (uint32_t)(kp * 2 + cx.lk);
            uint32_t a[4][4];
            #pragma unroll
            for (int mi = 0; mi < 4; mi++) {
                int row = cx.wr * 64 + mi * 16 + cx.lrow;
                uint32_t ad = aS + ((uint32_t)row << 7) + ((ch ^ (uint32_t)(row & 7)) << 4);
                LDSM_X4(a[mi][0], a[mi][1], a[mi][2], a[mi][3], ad);
            }
            uint32_t b[2][2];
            {
                int row = cx.wc * 16 + cx.lrow;
                uint32_t bd = bS + ((uint32_t)row << 7) + ((ch ^ (uint32_t)(row & 7)) << 4);
                uint32_t r0, r1, r2, r3;
                LDSM_X4(r0, r1, r2, r3, bd);
                b[0][0] = r0; b[1][0] = r1;
                b[0][1] = r2; b[1][1] = r3;
            }
            #pragma unroll
            for (int mi = 0; mi < 4; mi++)
                #pragma unroll
                for (int ni = 0; ni < 2; ni++)
                    MMA16816(acc[mi][ni][0], acc[mi][ni][1], acc[mi][ni][2], acc[mi][ni][3],
                             a[mi][0], a[mi][1], a[mi][2], a[mi][3], b[ni][0], b[ni][1]);
        }
    }
}

// ---------------- helpers --------------------------------------------------------

__global__ void convert_x_kernel(const float* __restrict__ x, __half* __restrict__ xh) {
    size_t i = ((size_t)blockIdx.x * blockDim.x + threadIdx.x) * 4;
    float4 v = *(const float4*)(x + i);
    union { __half2 h[2]; uint2 u; } w;
    w.h[0] = __floats2half2_rn(v.x, v.y);
    w.h[1] = __floats2half2_rn(v.z, v.w);
    *(uint2*)(xh + i) = w.u;
}

// skew (8192 blocks) + row_sum (2048 blocks), one launch
__global__ void prep_kernel(const float* __restrict__ W1, const float* __restrict__ W2,
                            __half* __restrict__ Ah, __half* __restrict__ Bneg,
                            float* __restrict__ part) {
    int bid = blockIdx.x;
    if (bid < 8192) {
        int gidx = bid * 256 + threadIdx.x;
        int z = gidx >> 20;
        int idx = gidx & (DD - 1);
        const float* W = z ? W2 : W1;
        int i = idx >> 10, j = idx & (D - 1);
        float a = 5.0f * (W[idx] - W[j * D + i]);   // 10 * 0.5 * (W - W^T)
        Ah[gidx]   = __float2half(a);
        Bneg[gidx] = __float2half(-a);
    } else {
        int b = bid - 8192;
        const float* src = (b < D) ? (W1 + (size_t)b * D) : (W2 + (size_t)(b - D) * D);
        __shared__ float sm[256];
        float s = 0.f;
        for (int j = threadIdx.x; j < D; j += 256) s += src[j];
        sm[threadIdx.x] = s;
        __syncthreads();
        for (int o = 128; o > 0; o >>= 1) {
            if (threadIdx.x < o) sm[threadIdx.x] += sm[threadIdx.x + o];
            __syncthreads();
        }
        if (threadIdx.x == 0) part[b] = sm[0];
    }
}

__global__ void pass_kernel(const float* __restrict__ part,
                            const float* __restrict__ theta,
                            float* __restrict__ out) {
    __shared__ float sm[1024];
    sm[threadIdx.x] = part[threadIdx.x] + part[threadIdx.x + 1024];
    __syncthreads();
    for (int o = 512; o > 0; o >>= 1) {
        if (threadIdx.x < o) sm[threadIdx.x] += sm[threadIdx.x + o];
        __syncthreads();
    }
    if (threadIdx.x == 0)
        out[0] = (sm[0] / 1048576.0f + theta[0]) * 1e-6f;
}

// ---------------- chain stage 1:  C = a @ (-a)^T = a^2  (128x64 tiles) ----------
// epilogue: P2 = half(C), ET = half(0.1C - a)
__global__ void __launch_bounds__(256, 2)
chain1_kernel(const __half* __restrict__ Ah, const __half* __restrict__ Bneg,
              __half* __restrict__ P2, __half* __restrict__ ET)
{
    extern __shared__ char dsm_raw[];
    char* dsm = (char*)(((uintptr_t)dsm_raw + 1023) & ~(uintptr_t)1023);
    ChainCtx cx = make_cctx(smem_u32(dsm));
    const size_t loff = (size_t)blockIdx.z * DD;
    const size_t rowBase = (size_t)blockIdx.y * 128;
    const int    colBase = blockIdx.x * 64;

    float acc[4][2][4];
    cgemm_main(cx, Ah + loff, Bneg + loff, rowBase, colBase, acc);

    const __half* Aeo = Ah + loff;
    __half* P2o = P2 + loff;
    __half* ETo = ET + loff;
    #pragma unroll
    for (int mi = 0; mi < 4; mi++) {
        const int rloc = cx.wr * 64 + mi * 16 + cx.grp;
        #pragma unroll
        for (int rr = 0; rr < 2; rr++) {
            const size_t grow = rowBase + rloc + rr * 8;
            #pragma unroll
            for (int ni = 0; ni < 2; ni++) {
                const int gcol = colBase + cx.wc * 16 + ni * 8 + cx.q * 2;
                float v0 = acc[mi][ni][rr * 2 + 0];
                float v1 = acc[mi][ni][rr * 2 + 1];
                const size_t idx = grow * D + gcol;
                *(__half2*)&P2o[idx] = __floats2half2_rn(v0, v1);
                __half2 a2 = *(const __half2*)&Aeo[idx];
                *(__half2*)&ETo[idx] = __floats2half2_rn(0.1f * v0 - __low2float(a2),
                                                         0.1f * v1 - __high2float(a2));
            }
        }
    }
}

// ---------------- chain stage 2:  C = P2 @ ET^T;  M = half(0.2a + 0.02P2 + 2e-3C)
__global__ void __launch_bounds__(256, 2)
chain2_kernel(const __half* __restrict__ P2, const __half* __restrict__ ET,
              const __half* __restrict__ Ah, __half* __restrict__ M)
{
    extern __shared__ char dsm_raw[];
    char* dsm = (char*)(((uintptr_t)dsm_raw + 1023) & ~(uintptr_t)1023);
    ChainCtx cx = make_cctx(smem_u32(dsm));
    const size_t loff = (size_t)blockIdx.z * DD;
    const size_t rowBase = (size_t)blockIdx.y * 128;
    const int    colBase = blockIdx.x * 64;

    float acc[4][2][4];
    cgemm_main(cx, P2 + loff, ET + loff, rowBase, colBase, acc);

    const __half* Aeo  = Ah + loff;
    const __half* P2o  = P2 + loff;
    __half* Mo = M + loff;
    #pragma unroll
    for (int mi = 0; mi < 4; mi++) {
        const int rloc = cx.wr * 64 + mi * 16 + cx.grp;
        #pragma unroll
        for (int rr = 0; rr < 2; rr++) {
            const size_t grow = rowBase + rloc + rr * 8;
            #pragma unroll
            for (int ni = 0; ni < 2; ni++) {
                const int gcol = colBase + cx.wc * 16 + ni * 8 + cx.q * 2;
                const size_t idx = grow * D + gcol;
                float2 a2  = __half22float2(*(const __half2*)&Aeo[idx]);
                float2 p2  = __half22float2(*(const __half2*)&P2o[idx]);
                float m0 = 0.2f * a2.x + 0.02f * p2.x + 2e-3f * acc[mi][ni][rr * 2 + 0];
                float m1 = 0.2f * a2.y + 0.02f * p2.y + 2e-3f * acc[mi][ni][rr * 2 + 1];
                *(__half2*)&Mo[idx] = __floats2half2_rn(m0, m1);
            }
        }
    }
}

// ---------------- rotW:  Wa = Rot (I + M1),  WaT = Wa^T -------------------------
__global__ void rotw_kernel(const __half* __restrict__ M1,
                            const float* __restrict__ theta,
                            __half* __restrict__ Wa, __half* __restrict__ WaT)
{
    __shared__ __half tile[64][65];
    float th = theta[0];
    float c = cosf(th), s = sinf(th);
    const int r0 = blockIdx.y * 64, c0 = blockIdx.x * 64;
    const int tid = threadIdx.x;
    #pragma unroll
    for (int i = 0; i < 16; i++) {
        int idx = tid + (i << 8);
        int r = idx >> 6, cc = idx & 63;
        int gr = r0 + r, gc = c0 + cc;
        int gp = gr ^ 1;
        float xr = __half2float(M1[(size_t)gr * D + gc]) + (gr == gc ? 1.f : 0.f);
        float xp = __half2float(M1[(size_t)gp * D + gc]) + (gp == gc ? 1.f : 0.f);
        float wa = (gr & 1) ? (c * xr + s * xp) : (c * xr - s * xp);
        __half h = __float2half(wa);
        Wa[(size_t)gr * D + gc] = h;
        tile[r][cc] = h;
    }
    __syncthreads();
    #pragma unroll
    for (int i = 0; i < 16; i++) {
        int idx = tid + (i << 8);
        int tr = idx >> 6, tc = idx & 63;
        WaT[(size_t)(c0 + tr) * D + (r0 + tc)] = tile[tc][tr];
    }
}

// ---------------- buildW:  C = M2 @ Wa;  W = half(Wa + C)  (128x64 tiles) -------
__global__ void __launch_bounds__(256, 2)
buildw_kernel(const __half* __restrict__ M2, const __half* __restrict__ WaT,
              const __half* __restrict__ Wa, __half* __restrict__ W)
{
    extern __shared__ char dsm_raw[];
    char* dsm = (char*)(((uintptr_t)dsm_raw + 1023) & ~(uintptr_t)1023);
    ChainCtx cx = make_cctx(smem_u32(dsm));
    const size_t rowBase = (size_t)blockIdx.y * 128;
    const int    colBase = blockIdx.x * 64;

    float acc[4][2][4];
    cgemm_main(cx, M2, WaT, rowBase, colBase, acc);

    #pragma unroll
    for (int mi = 0; mi < 4; mi++) {
        const int rloc = cx.wr * 64 + mi * 16 + cx.grp;
        #pragma unroll
        for (int rr = 0; rr < 2; rr++) {
            const size_t grow = rowBase + rloc + rr * 8;
            #pragma unroll
            for (int ni = 0; ni < 2; ni++) {
                const int gcol = colBase + cx.wc * 16 + ni * 8 + cx.q * 2;
                const size_t idx = grow * D + gcol;
                float2 wv = __half22float2(*(const __half2*)&Wa[idx]);
                *(__half2*)&W[idx] = __floats2half2_rn(wv.x + acc[mi][ni][rr * 2 + 0],
                                                       wv.y + acc[mi][ni][rr * 2 + 1]);
            }
        }
    }
}

// ---------------- the ONE big GEMM (64x64 warp tile, 128 threads) ---------------
// out = xh @ W^T + pass      (fragment-pipelined inner loop)
__global__ void __launch_bounds__(128, 2)
bigw_kernel(const __half* __restrict__ xh, const __half* __restrict__ W,
            const float* __restrict__ passv, float* __restrict__ out)
{
    extern __shared__ char dsm_raw[];
    char* dsm = (char*)(((uintptr_t)dsm_raw + 1023) & ~(uintptr_t)1023);
    const uint32_t sbase = smem_u32(dsm);

    const int tid  = threadIdx.x;
    const int w    = tid >> 5, lane = tid & 31;
    const int wr = w >> 1, wc = w & 1;            // 2x2 warp grid, 64x64 each
    const int grp = lane >> 2, q = lane & 3;
    const int lrow = lane & 15, lk = lane >> 4;

    const size_t rowBase = (size_t)blockIdx.y * 128;
    const int    colBase = blockIdx.x * 128;

    float acc[4][8][4];
    #pragma unroll
    for (int a = 0; a < 4; a++)
        #pragma unroll
        for (int b = 0; b < 8; b++)
            #pragma unroll
            for (int c = 0; c < 4; c++) acc[a][b][c] = 0.f;

    auto load_tile = [&](int kt) {
        const int stage = kt % 3;
        const int k0 = kt * TBK;
        #pragma unroll
        for (int i = 0; i < 16; i++) {
            int id  = tid + (i << 7);
            int isB = id >> 10;
            int rc  = id & 1023;
            int row = rc >> 3, c = rc & 7;
            uint32_t sw = ((uint32_t)row << 7) | (((uint32_t)(c ^ (row & 7))) << 4);
            const __half* g = (isB ? (W  + (size_t)(colBase + row) * D)
                                   : (xh + (rowBase + row) * (size_t)D)) + k0 + (c << 3);
            uint32_t s = sbase + stage * STAGEB + (isB << 14) + sw;
            asm volatile("cp.async.cg.shared.global [%0], [%1], 16;\n" :: "r"(s), "l"(g));
        }
        asm volatile("cp.async.commit_group;\n");
    };

    load_tile(0);
    load_tile(1);

    uint32_t af[2][4][4];
    uint32_t bf[2][8][2];

    auto load_frags = [&](uint32_t aS, uint32_t bS, int kp, int buf) {
        const uint32_t ch = (uint32_t)(kp * 2 + lk);
        #pragma unroll
        for (int mi = 0; mi < 4; mi++) {
            int row = wr * 64 + mi * 16 + lrow;
            uint32_t ad = aS + ((uint32_t)row << 7) + ((ch ^ (uint32_t)(row & 7)) << 4);
            LDSM_X4(af[buf][mi][0], af[buf][mi][1], af[buf][mi][2], af[buf][mi][3], ad);
        }
        #pragma unroll
        for (int np = 0; np < 4; np++) {
            int row = wc * 64 + np * 16 + lrow;
            uint32_t bd = bS + ((uint32_t)row << 7) + ((ch ^ (uint32_t)(row & 7)) << 4);
            uint32_t r0, r1, r2, r3;
            LDSM_X4(r0, r1, r2, r3, bd);
            bf[buf][np * 2 + 0][0] = r0; bf[buf][np * 2 + 1][0] = r1;
            bf[buf][np * 2 + 0][1] = r2; bf[buf][np * 2 + 1][1] = r3;
        }
    };

    for (int kt = 0; kt < KT; kt++) {
        if (kt == KT - 1) asm volatile("cp.async.wait_group 0;\n");
        else              asm volatile("cp.async.wait_group 1;\n");
        __syncthreads();
        if (kt + 2 < KT) load_tile(kt + 2);

        const uint32_t aS = sbase + (kt % 3) * STAGEB;
        const uint32_t bS = aS + 16384;

        load_frags(aS, bS, 0, 0);
        #pragma unroll
        for (int kp = 0; kp < 4; kp++) {
            const int cur = kp & 1;
            if (kp < 3) load_frags(aS, bS, kp + 1, cur ^ 1);
            #pragma unroll
            for (int mi = 0; mi < 4; mi++)
                #pragma unroll
                for (int ni = 0; ni < 8; ni++)
                    MMA16816(acc[mi][ni][0], acc[mi][ni][1], acc[mi][ni][2], acc[mi][ni][3],
                             af[cur][mi][0], af[cur][mi][1], af[cur][mi][2], af[cur][mi][3],
                             bf[cur][ni][0], bf[cur][ni][1]);
        }
    }

    const float pv = passv[0];
    #pragma unroll
    for (int mi = 0; mi < 4; mi++) {
        const int rloc = wr * 64 + mi * 16 + grp;
        #pragma unroll
        for (int rr = 0; rr < 2; rr++) {
            const size_t grow = rowBase + rloc + rr * 8;
            #pragma unroll
            for (int ni = 0; ni < 8; ni++) {
                const int gcol = colBase + wc * 64 + ni * 8 + q * 2;
                const size_t idx = grow * D + gcol;
                float2 o;
                o.x = acc[mi][ni][rr * 2 + 0] + pv;
                o.y = acc[mi][ni][rr * 2 + 1] + pv;
                *(float2*)&out[idx] = o;
            }
        }
    }
}

// ---------------- host launcher (sequential; no stream/event creation) ----------

extern "C" void kernel_launch(void* const* d_in, const int* in_sizes, int n_in,
                              void* d_out, int out_size) {
    const float* x     = (const float*)d_in[0];
    const float* u1    = (const float*)d_in[1];
    const float* u2    = (const float*)d_in[2];
    const float* theta = (const float*)d_in[3];
    float* out = (float*)d_out;

    __half *xh, *Ah, *Bneg, *P2, *ET, *M, *Wa, *WaT, *W;
    float *part, *pass;
    cudaGetSymbolAddress((void**)&xh,   g_xh);
    cudaGetSymbolAddress((void**)&Ah,   g_Ah);
    cudaGetSymbolAddress((void**)&Bneg, g_Bneg);
    cudaGetSymbolAddress((void**)&P2,   g_P2);
    cudaGetSymbolAddress((void**)&ET,   g_ET);
    cudaGetSymbolAddress((void**)&M,    g_M);
    cudaGetSymbolAddress((void**)&Wa,   g_Wa);
    cudaGetSymbolAddress((void**)&WaT,  g_WaT);
    cudaGetSymbolAddress((void**)&W,    g_W);
    cudaGetSymbolAddress((void**)&part, g_part);
    cudaGetSymbolAddress((void**)&pass, g_pass);

    cudaFuncSetAttribute(chain1_kernel, cudaFuncAttributeMaxDynamicSharedMemorySize, CSMEM);
    cudaFuncSetAttribute(chain2_kernel, cudaFuncAttributeMaxDynamicSharedMemorySize, CSMEM);
    cudaFuncSetAttribute(buildw_kernel, cudaFuncAttributeMaxDynamicSharedMemorySize, CSMEM);
    cudaFuncSetAttribute(bigw_kernel,   cudaFuncAttributeMaxDynamicSharedMemorySize, SMEMSZ);

    // skew (a = 10A, -a) + row sums
    prep_kernel<<<8192 + 2048, 256>>>(u1, u2, Ah, Bneg, part);
    // passthrough scalar
    pass_kernel<<<1, 1024>>>(part, theta, pass);

    // fp16 inputs
    convert_x_kernel<<<(int)(((size_t)NROWS * D) / 4 / 256), 256>>>(x, xh);

    // Neumann chain (both layers), 128x64 tiles -> 256 blocks each
    chain1_kernel<<<dim3(16, 8, 2), 256, CSMEM>>>(Ah, Bneg, P2, ET);
    chain2_kernel<<<dim3(16, 8, 2), 256, CSMEM>>>(P2, ET, Ah, M);

    // Wa = Rot (I + M1), WaT = Wa^T
    rotw_kernel<<<dim3(16, 16), 256>>>(M, theta, Wa, WaT);
    // W = (I + M2) Wa = Wa + M2 @ Wa   (128x64 tiles -> 128 blocks)
    buildw_kernel<<<dim3(16, 8), 256, CSMEM>>>(M + DD, WaT, Wa, W);

    // out = x @ W^T + passthrough
    bigw_kernel<<<dim3(D / 128, NROWS / 128), 128, SMEMSZ>>>(xh, W, pass, out);
}